// round 11
// baseline (speedup 1.0000x reference)
#include <cuda_runtime.h>
#include <cuda_fp16.h>
#include <cuda_bf16.h>
#include <cstdint>

// ---------------------------------------------------------------------------
// Problem constants
// ---------------------------------------------------------------------------
#define SEQ   2048
#define BATCH 16
#define DIN   512
#define HID   512
#define MROWS (SEQ*BATCH)       // 32768
#define NCOLS (3*HID*2)         // 3072
#define KDIM  DIN               // 512

// Feature gate: tcgen05 only exists in an arch-specific (sm_103a/sm_100a) pass.
#if defined(__CUDA_ARCH__) && (defined(__CUDA_ARCH_FEAT_SM103_ALL) || defined(__CUDA_ARCH_FEAT_SM100_ALL))
#define HAS_TCGEN05 1
#else
#define HAS_TCGEN05 0
#endif

// Scratch (static device arrays; no allocation allowed)
__device__ __half g_G[(size_t)MROWS * NCOLS];   // pre-activation gates (fp16)
__device__ __half g_Xh[(size_t)MROWS * KDIM];   // X in fp16
__device__ __half g_Wh[(size_t)NCOLS * KDIM];   // [W_fw; W_bw] in fp16

// Chunked-scan aggregates: 16384 lanes x 8 chunks, layout [chunk][lane]
#define NLANE 16384
#define NCHK  8
#define CHLEN (SEQ / NCHK)      // 256
__device__ float g_A[NCHK * NLANE];
__device__ float g_C[NCHK * NLANE];

// ---------------------------------------------------------------------------
// Probe kernel: static smem size tells the host whether the loaded device
// code came from the arch-specific (tcgen05-capable) pass.
// ---------------------------------------------------------------------------
__global__ void probe_kernel(float* p) {
#if HAS_TCGEN05
    __shared__ volatile float s[2048];
#else
    __shared__ volatile float s[64];
#endif
    s[threadIdx.x & 63] = p[0];
    p[1] = s[(threadIdx.x + 1) & 63];
}

// ---------------------------------------------------------------------------
// Common helpers
// ---------------------------------------------------------------------------
__device__ __forceinline__ uint32_t smem_to_u32(const void* p) {
    uint32_t a;
    asm("{ .reg .u64 t; cvta.to.shared.u64 t, %1; cvt.u32.u64 %0, t; }" : "=r"(a) : "l"(p));
    return a;
}

__device__ __forceinline__ float ex2f(float x) {
    float y; asm("ex2.approx.ftz.f32 %0, %1;" : "=f"(y) : "f"(x)); return y;
}
__device__ __forceinline__ float rcpf(float x) {
    float y; asm("rcp.approx.ftz.f32 %0, %1;" : "=f"(y) : "f"(x)); return y;
}
__device__ __forceinline__ float sigm_(float x) {
    return rcpf(1.0f + ex2f(-1.4426950408889634f * x));
}
__device__ __forceinline__ float tanh_(float x) {
    return fmaf(2.0f, rcpf(1.0f + ex2f(-2.8853900817779268f * x)), -1.0f);
}

// ---------------------------------------------------------------------------
// Kernel 0: fp32 -> fp16 conversion (X, W_fw, W_bw)
// ---------------------------------------------------------------------------
__global__ __launch_bounds__(256) void cvt_kernel(
    const float* __restrict__ X,
    const float* __restrict__ Wfw,
    const float* __restrict__ Wbw)
{
    const long long NX = (long long)MROWS * KDIM;     // 16777216
    const long long NW = (long long)(3 * HID) * KDIM; // 786432 per direction
    long long i = ((long long)blockIdx.x * blockDim.x + threadIdx.x) * 4;

    const float* src;
    __half* dst;
    if (i < NX)           { src = X   + i;             dst = g_Xh + i; }
    else if (i < NX + NW) { src = Wfw + (i - NX);      dst = g_Wh + (i - NX); }
    else                  { src = Wbw + (i - NX - NW); dst = g_Wh + (i - NX); }

    float4 v = __ldcs((const float4*)src);
    *(__half2*)dst       = __floats2half2_rn(v.x, v.y);
    *(__half2*)(dst + 2) = __floats2half2_rn(v.z, v.w);
}

// ===========================================================================
// GEMM path A: tcgen05, M=128 x N=256 tiles, 1 CTA/SM, 4-stage cp.async
// pipeline, TMEM double-buffered epilogue overlap.
// Tile order: all z/f-gate tiles first, then PDL-trigger, then o-gate tiles
// (so scan_phase1 can overlap the o-gate third of the GEMM).
// ===========================================================================
#define GBM 128
#define GBN 256
#define GBK 64
#define NKCH (KDIM / GBK)        // 8
#define STAGES 4
#define STAGE_A 16384            // 128 rows x 128B
#define STAGE_B 32768            // 256 rows x 128B
#define SMEM_A_OFF 1024
#define SMEM_B_OFF (1024 + STAGES * STAGE_A)          // 66560
#define GEMM_SMEM  (SMEM_B_OFF + STAGES * STAGE_B)    // 197632
#define N_MTILE (MROWS / GBM)    // 256
#define N_NTILE (NCOLS / GBN)    // 12
#define N_ZF_TILES (N_MTILE * 8)     // 2048 (z,f gates, both dirs)
#define N_TILES (N_MTILE * N_NTILE)  // 3072
#define GEMM_CTAS 148
#define GEMM_THREADS 256

#if HAS_TCGEN05
#define SMEM_SWIZZLE_128B(o) ((o) ^ (((o) >> 3) & 0x70))

static constexpr uint64_t SMEM_DESC_BASE_SW128 =
    (uint64_t(2) << 61) | (uint64_t(1) << 46) | (uint64_t(64) << 32) | (uint64_t(1) << 16);
#define MAKE_SMEM_DESC(base_addr) \
    (SMEM_DESC_BASE_SW128 | ((uint64_t)((base_addr) >> 4) & 0x3FFF))

#define MBARRIER_INIT(addr, cnt) \
    asm volatile("mbarrier.init.shared.b64 [%0], %1;" :: "r"((uint32_t)(addr)), "r"((uint32_t)(cnt)) : "memory")

__device__ __forceinline__ void mbar_wait(uint32_t mbar, int parity) {
    uint32_t done;
    asm volatile(
        "{\n\t.reg .pred p;\n\t"
        "mbarrier.try_wait.parity.acquire.cta.shared::cta.b64 p, [%1], %2;\n\t"
        "selp.b32 %0, 1, 0, p;\n\t}"
        : "=r"(done) : "r"(mbar), "r"((uint32_t)parity) : "memory");
    if (!done) {
        asm volatile(
            "{\n\t.reg .pred P1;\n\t"
            "WAIT_LOOP_%=:\n\t"
            "mbarrier.try_wait.parity.acquire.cta.shared::cta.b64 P1, [%0], %1, 0x989680;\n\t"
            "@P1 bra.uni WAIT_DONE_%=;\n\t"
            "bra.uni WAIT_LOOP_%=;\n\t"
            "WAIT_DONE_%=:\n\t}"
            :: "r"(mbar), "r"((uint32_t)parity) : "memory");
    }
}

__device__ __forceinline__ uint32_t elect_one_pred() {
    uint32_t pred;
    asm volatile(
        "{\n\t.reg .pred p;\n\t"
        "elect.sync _|p, 0xFFFFFFFF;\n\t"
        "selp.b32 %0, 1, 0, p;\n\t}"
        : "=r"(pred));
    return pred;
}

#define TCGEN05_LD_32X32B_X32(r, tmem_addr) \
    asm volatile( \
        "tcgen05.ld.sync.aligned.32x32b.x32.b32 " \
        "{%0, %1, %2, %3, %4, %5, %6, %7, " \
        " %8, %9, %10, %11, %12, %13, %14, %15, " \
        " %16, %17, %18, %19, %20, %21, %22, %23, " \
        " %24, %25, %26, %27, %28, %29, %30, %31}, [%32];" \
        : "=r"((r)[0]),  "=r"((r)[1]),  "=r"((r)[2]),  "=r"((r)[3]), \
          "=r"((r)[4]),  "=r"((r)[5]),  "=r"((r)[6]),  "=r"((r)[7]), \
          "=r"((r)[8]),  "=r"((r)[9]),  "=r"((r)[10]), "=r"((r)[11]), \
          "=r"((r)[12]), "=r"((r)[13]), "=r"((r)[14]), "=r"((r)[15]), \
          "=r"((r)[16]), "=r"((r)[17]), "=r"((r)[18]), "=r"((r)[19]), \
          "=r"((r)[20]), "=r"((r)[21]), "=r"((r)[22]), "=r"((r)[23]), \
          "=r"((r)[24]), "=r"((r)[25]), "=r"((r)[26]), "=r"((r)[27]), \
          "=r"((r)[28]), "=r"((r)[29]), "=r"((r)[30]), "=r"((r)[31]) \
        : "r"(tmem_addr))

// idesc: dtype=F32 (1<<4), atype=btype=F16 (0), N=128 -> N/8<<17, M=128 -> M/16<<24
#define IDESC_F16 ((1u << 4) | ((128u / 8u) << 17) | ((128u / 16u) << 24))

__device__ __forceinline__ void mma_f16_ss(uint32_t d_tmem, uint64_t a_desc, uint64_t b_desc,
                                           uint32_t idesc, bool accum) {
    uint32_t en = accum ? 1u : 0u;
    asm volatile(
        "{\n\t.reg .pred p;\n\t"
        "setp.ne.u32 p, %4, 0;\n\t"
        "tcgen05.mma.cta_group::1.kind::f16 [%0], %1, %2, %3, {%5, %5, %5, %5}, p;\n\t}"
        :: "r"(d_tmem), "l"(a_desc), "l"(b_desc), "r"(idesc), "r"(en), "r"(0u)
        : "memory");
}

__device__ __forceinline__ void cp_async16(uint32_t dst, const void* src) {
    asm volatile("cp.async.cg.shared.global [%0], [%1], 16;" :: "r"(dst), "l"(src) : "memory");
}
__device__ __forceinline__ void cp_commit() {
    asm volatile("cp.async.commit_group;" ::: "memory");
}
template<int N> __device__ __forceinline__ void cp_wait() {
    asm volatile("cp.async.wait_group %0;" :: "n"(N) : "memory");
}

// Load one K-chunk (A: 128x64 halfs, B: 256x64 halfs) into stage st.
__device__ __forceinline__ void load_stage(uint32_t smem_base, int st, int kt,
                                           int m0, int n0, int tid)
{
    const __half* Asrc = g_Xh + (size_t)m0 * KDIM + kt * GBK;
    const __half* Bsrc = g_Wh + (size_t)n0 * KDIM + kt * GBK;
    uint32_t abase = smem_base + SMEM_A_OFF + st * STAGE_A;
    uint32_t bbase = smem_base + SMEM_B_OFF + st * STAGE_B;
#pragma unroll
    for (int i = 0; i < 4; i++) {                 // A: 1024 16B-chunks
        int chunk = i * GEMM_THREADS + tid;
        int row   = chunk >> 3;
        int c16   = chunk & 7;
        uint32_t off = SMEM_SWIZZLE_128B((uint32_t)(row * 128 + c16 * 16));
        cp_async16(abase + off, Asrc + (size_t)row * KDIM + c16 * 8);
    }
#pragma unroll
    for (int i = 0; i < 8; i++) {                 // B: 2048 16B-chunks
        int chunk = i * GEMM_THREADS + tid;
        int row   = chunk >> 3;
        int c16   = chunk & 7;
        uint32_t off = SMEM_SWIZZLE_128B((uint32_t)(row * 128 + c16 * 16));
        cp_async16(bbase + off, Bsrc + (size_t)row * KDIM + c16 * 8);
    }
    cp_commit();
}

// Epilogue: TMEM fp32 (128 lanes x 256 cols) -> fp16 -> streaming store.
__device__ __forceinline__ void epilogue_tile(uint32_t tmem_d, int m0, int n0,
                                              int wid, int lid)
{
    asm volatile("tcgen05.fence::after_thread_sync;" ::: "memory");
    const int sub     = wid & 3;
    const int colhalf = wid >> 2;
    const int m = m0 + sub * 32 + lid;
    __half* gout = g_G + (size_t)m * NCOLS + n0 + colhalf * 128;
    const uint32_t tbase = tmem_d + colhalf * 128;
#pragma unroll
    for (int c0 = 0; c0 < 128; c0 += 32) {
        uint32_t d[32];
        TCGEN05_LD_32X32B_X32(d, tbase + c0);
        asm volatile("tcgen05.wait::ld.sync.aligned;" ::: "memory");
        uint32_t hp[16];
#pragma unroll
        for (int c = 0; c < 16; c++) {
            __half2 h2 = __floats2half2_rn(__uint_as_float(d[2 * c]),
                                           __uint_as_float(d[2 * c + 1]));
            hp[c] = *(uint32_t*)&h2;
        }
#pragma unroll
        for (int q = 0; q < 4; q++) {
            uint4 v = make_uint4(hp[q * 4], hp[q * 4 + 1], hp[q * 4 + 2], hp[q * 4 + 3]);
            __stcs((uint4*)(gout + c0 + q * 8), v);
        }
    }
    asm volatile("tcgen05.fence::before_thread_sync;" ::: "memory");
}
#endif  // HAS_TCGEN05

#define MBAR(s) (smem_base + 16 + (s) * 8)
#define SLOT_FINAL 4

__global__ void __launch_bounds__(GEMM_THREADS, 1) __cluster_dims__(1, 1, 1) gemm_tc_kernel()
{
#if HAS_TCGEN05
    extern __shared__ char smem[];
    uint32_t smem_base = smem_to_u32(smem);
    const int tid = threadIdx.x;
    const int wid = tid >> 5;
    const int lid = tid & 31;

    if (tid < 5) MBARRIER_INIT(MBAR(tid), 1);   // 0-3: stage reuse, 4: tile-final
    if (wid == 0) {
        asm volatile("tcgen05.alloc.cta_group::1.sync.aligned.shared::cta.b32 [%0], %1;"
            :: "r"(smem_base), "r"(512u) : "memory");
        asm volatile("tcgen05.relinquish_alloc_permit.cta_group::1.sync.aligned;");
    }
    __syncthreads();

    uint32_t tmem;
    asm volatile("ld.shared.b32 %0, [%1];" : "=r"(tmem) : "r"(smem_base));

    int ph[5] = {0, 0, 0, 0, 0};
    int buf = 0;
    int prev_m0 = 0, prev_n0 = 0;
    bool has_prev = false;
    bool prev_last_zf = false;   // prev tile is this CTA's last z/f tile

    for (int tt = blockIdx.x; tt < N_TILES; tt += GEMM_CTAS) {
        // Tile map: tt < 2048 -> z/f gate tiles (nt in {0,1,2,3,6,7,8,9});
        //           tt >= 2048 -> o gate tiles (nt in {4,5,10,11}).
        int mt, nt;
        if (tt < N_ZF_TILES) {
            mt = tt >> 3;
            int j = tt & 7;
            nt = j + (j >= 4 ? 2 : 0);
        } else {
            int u = tt - N_ZF_TILES;
            mt = u >> 2;
            int j = u & 3;
            nt = (j < 2) ? (j + 4) : (j + 8);
        }
        const int m0 = mt * GBM;
        const int n0 = nt * GBN;
        const uint32_t tmem_d = tmem + buf * 256;

        load_stage(smem_base, 0, 0, m0, n0, tid);
        load_stage(smem_base, 1, 1, m0, n0, tid);
        if (has_prev) { mbar_wait(MBAR(SLOT_FINAL), ph[SLOT_FINAL]); ph[SLOT_FINAL] ^= 1; }
        load_stage(smem_base, 2, 2, m0, n0, tid);

#pragma unroll
        for (int kt = 0; kt < NKCH; kt++) {
            const int st = kt % STAGES;
            if (kt == NKCH - 1)      cp_wait<0>();
            else if (kt == NKCH - 2) cp_wait<1>();
            else                     cp_wait<2>();
            __syncthreads();
            asm volatile("fence.proxy.async.shared::cta;" ::: "memory");

            if (wid == 0) {
                if (elect_one_pred()) {
                    uint64_t ad = MAKE_SMEM_DESC(smem_base + SMEM_A_OFF + st * STAGE_A);
                    uint64_t bd = MAKE_SMEM_DESC(smem_base + SMEM_B_OFF + st * STAGE_B);
#pragma unroll
                    for (int nh = 0; nh < 2; nh++)
#pragma unroll
                        for (int k = 0; k < 4; k++)   // 4 x K=16 per 64-half chunk
                            mma_f16_ss(tmem_d + nh * 128,
                                       ad + k * 2,
                                       bd + nh * 1024 + k * 2,   // +128 B-rows
                                       IDESC_F16,
                                       !(kt == 0 && k == 0));
                    asm volatile(
                        "tcgen05.commit.cta_group::1.mbarrier::arrive::one.shared::cluster.b64 [%0];"
                        :: "r"(MBAR(kt == NKCH - 1 ? SLOT_FINAL : st)) : "memory");
                }
            }

            if (kt >= 1) {
                const int ws = (kt - 1) % STAGES;
                mbar_wait(MBAR(ws), ph[ws]); ph[ws] ^= 1;
            }
            if (kt + 3 < NKCH)
                load_stage(smem_base, (kt + 3) % STAGES, kt + 3, m0, n0, tid);
        }

        // Drain the PREVIOUS tile's accumulator while this tile's MMAs run.
        if (has_prev) {
            epilogue_tile(tmem + (buf ^ 1) * 256, prev_m0, prev_n0, wid, lid);
            if (prev_last_zf) {
                // All z/f gate outputs of this CTA are now stored: let the
                // PDL-dependent scan_phase1 launch while we do o tiles.
                __syncthreads();
                cudaTriggerProgrammaticLaunchCompletion();
            }
        }

        has_prev = true;
        prev_m0 = m0; prev_n0 = n0;
        prev_last_zf = (tt < N_ZF_TILES) && (tt + GEMM_CTAS >= N_ZF_TILES);
        buf ^= 1;
    }

    // Tail: drain the last tile.
    if (has_prev) {
        mbar_wait(MBAR(SLOT_FINAL), ph[SLOT_FINAL]); ph[SLOT_FINAL] ^= 1;
        epilogue_tile(tmem + (buf ^ 1) * 256, prev_m0, prev_n0, wid, lid);
        if (prev_last_zf) {
            __syncthreads();
            cudaTriggerProgrammaticLaunchCompletion();
        }
    }

    __syncthreads();
    if (wid == 0)
        asm volatile("tcgen05.dealloc.cta_group::1.sync.aligned.b32 %0, %1;" :: "r"(tmem), "r"(512u));
#endif  // HAS_TCGEN05
}

// ===========================================================================
// GEMM path B (fallback, baseline ISA): fp16 mma.sync.m16n8k16
// ===========================================================================
#define BM 128
#define BN 128
#define BK 32
#define HPAD 40   // 32 + 8 halves padding

__global__ __launch_bounds__(256) void gemm_fp16_kernel()
{
    __shared__ __half sA[BM][HPAD];
    __shared__ __half sB[BN][HPAD];

    const int tid  = threadIdx.x;
    const int n0   = blockIdx.x * BN;
    const int m0   = blockIdx.y * BM;

    const __half* Asrc = g_Xh + (size_t)m0 * KDIM;
    const __half* Bsrc = g_Wh + (size_t)n0 * KDIM;

    const int warp = tid >> 5;
    const int lane = tid & 31;
    const int wm   = warp >> 1;
    const int wn   = warp & 1;
    const int lr   = lane >> 2;
    const int lc   = lane & 3;

    float4 ra[2], rb[2];

#pragma unroll
    for (int i = 0; i < 2; i++) {
        int slot = tid + i * 256;
        int row  = slot >> 2;
        int c8   = slot & 3;
        ra[i] = *(const float4*)(Asrc + (size_t)row * KDIM + c8 * 8);
        rb[i] = *(const float4*)(Bsrc + (size_t)row * KDIM + c8 * 8);
    }
#pragma unroll
    for (int i = 0; i < 2; i++) {
        int slot = tid + i * 256;
        int row  = slot >> 2;
        int c8   = slot & 3;
        *(float4*)&sA[row][c8 * 8] = ra[i];
        *(float4*)&sB[row][c8 * 8] = rb[i];
    }
    __syncthreads();

    float acc[2][8][4];
#pragma unroll
    for (int mt = 0; mt < 2; mt++)
#pragma unroll
        for (int nt = 0; nt < 8; nt++)
#pragma unroll
            for (int r = 0; r < 4; r++) acc[mt][nt][r] = 0.0f;

    const int NK = KDIM / BK;  // 16
    for (int kt = 0; kt < NK; kt++) {
        if (kt < NK - 1) {
#pragma unroll
            for (int i = 0; i < 2; i++) {
                int slot = tid + i * 256;
                int row  = slot >> 2;
                int c8   = slot & 3;
                ra[i] = *(const float4*)(Asrc + (size_t)row * KDIM + (kt + 1) * BK + c8 * 8);
                rb[i] = *(const float4*)(Bsrc + (size_t)row * KDIM + (kt + 1) * BK + c8 * 8);
            }
        }

#pragma unroll
        for (int ks = 0; ks < 2; ks++) {
            const int kc = ks * 16 + lc * 2;
            uint32_t afr[2][4];
            uint32_t bfr[8][2];
#pragma unroll
            for (int mt = 0; mt < 2; mt++) {
                int r = wm * 32 + mt * 16 + lr;
                afr[mt][0] = *(const uint32_t*)&sA[r    ][kc    ];
                afr[mt][1] = *(const uint32_t*)&sA[r + 8][kc    ];
                afr[mt][2] = *(const uint32_t*)&sA[r    ][kc + 8];
                afr[mt][3] = *(const uint32_t*)&sA[r + 8][kc + 8];
            }
#pragma unroll
            for (int nt = 0; nt < 8; nt++) {
                int nr = wn * 64 + nt * 8 + lr;
                bfr[nt][0] = *(const uint32_t*)&sB[nr][kc    ];
                bfr[nt][1] = *(const uint32_t*)&sB[nr][kc + 8];
            }
#pragma unroll
            for (int mt = 0; mt < 2; mt++)
#pragma unroll
                for (int nt = 0; nt < 8; nt++)
                    asm volatile(
                        "mma.sync.aligned.m16n8k16.row.col.f32.f16.f16.f32 "
                        "{%0,%1,%2,%3}, {%4,%5,%6,%7}, {%8,%9}, {%0,%1,%2,%3};"
                        : "+f"(acc[mt][nt][0]), "+f"(acc[mt][nt][1]),
                          "+f"(acc[mt][nt][2]), "+f"(acc[mt][nt][3])
                        : "r"(afr[mt][0]), "r"(afr[mt][1]), "r"(afr[mt][2]), "r"(afr[mt][3]),
                          "r"(bfr[nt][0]), "r"(bfr[nt][1]));
        }

        __syncthreads();
        if (kt < NK - 1) {
#pragma unroll
            for (int i = 0; i < 2; i++) {
                int slot = tid + i * 256;
                int row  = slot >> 2;
                int c8   = slot & 3;
                *(float4*)&sA[row][c8 * 8] = ra[i];
                *(float4*)&sB[row][c8 * 8] = rb[i];
            }
            __syncthreads();
        }
    }

#pragma unroll
    for (int mt = 0; mt < 2; mt++) {
#pragma unroll
        for (int nt = 0; nt < 8; nt++) {
            int r0  = m0 + wm * 32 + mt * 16 + lr;
            int col = n0 + wn * 64 + nt * 8 + lc * 2;
            __half2 h0 = __floats2half2_rn(acc[mt][nt][0], acc[mt][nt][1]);
            __half2 h1 = __floats2half2_rn(acc[mt][nt][2], acc[mt][nt][3]);
            *(__half2*)(g_G + (size_t)r0 * NCOLS + col)       = h0;
            *(__half2*)(g_G + (size_t)(r0 + 8) * NCOLS + col) = h1;
        }
    }
}

// ===========================================================================
// Chunked scan: 2 passes. Each thread handles an (h, h+1) pair via half2.
// p1 computes per-chunk (A, C); p3 inlines the serial chunk combine (A/C are
// ~1MB, L2-hot) and produces Y. 65536 threads each.
// ===========================================================================
#define SCH 8   // inner prefetch chunk

__global__ __launch_bounds__(256) void scan_phase1(
    const float* __restrict__ bfw,
    const float* __restrict__ bbw)
{
    // PDL: block here until the GEMM's z/f tiles are stored (trigger fired).
    cudaGridDependencySynchronize();

    const int t    = blockIdx.x * 256 + threadIdx.x;   // 0..65535
    const int h    = (t & 255) * 2;
    const int c    = (t >> 8) & 7;
    const int bi   = (t >> 11) & 15;
    const int dir  = t >> 15;
    const int lane = dir * 8192 + bi * 512 + h;

    const float* bias = dir ? bbw : bfw;
    const float2 bz = *(const float2*)(bias + h);
    const float2 bf = *(const float2*)(bias + HID + h);

    const int s0 = dir ? (SEQ - 1 - c * CHLEN) : (c * CHLEN);
    const long long step2 = (dir ? -(long long)(BATCH * NCOLS) : (long long)(BATCH * NCOLS)) / 2;
    const __half2* gp = (const __half2*)(g_G + ((long long)(s0 * BATCH + bi)) * NCOLS
                                         + dir * 3 * HID + h);

    __half2 zc[SCH], fc[SCH];
#pragma unroll
    for (int j = 0; j < SCH; j++) {
        zc[j] = __ldcs(gp);
        fc[j] = __ldcs(gp + HID / 2);
        gp += step2;
    }

    float hs0 = 0.0f, hs1 = 0.0f, A0 = 1.0f, A1 = 1.0f;
    const int NIT = CHLEN / SCH;  // 32
    for (int it = 0; it < NIT; it++) {
        __half2 zn[SCH], fn[SCH];
        if (it < NIT - 1) {
#pragma unroll
            for (int j = 0; j < SCH; j++) {
                zn[j] = __ldcs(gp);
                fn[j] = __ldcs(gp + HID / 2);
                gp += step2;
            }
        }
#pragma unroll
        for (int j = 0; j < SCH; j++) {
            float2 zv = __half22float2(zc[j]);
            float2 fv = __half22float2(fc[j]);
            float z0 = tanh_(zv.x + bz.x), z1 = tanh_(zv.y + bz.y);
            float f0 = sigm_(fv.x + bf.x), f1 = sigm_(fv.y + bf.y);
            hs0 = fmaf(f0, z0 - hs0, hs0);
            hs1 = fmaf(f1, z1 - hs1, hs1);
            A0 *= (1.0f - f0);
            A1 *= (1.0f - f1);
        }
#pragma unroll
        for (int j = 0; j < SCH; j++) { zc[j] = zn[j]; fc[j] = fn[j]; }
    }

    *(float2*)&g_A[c * NLANE + lane] = make_float2(A0, A1);
    *(float2*)&g_C[c * NLANE + lane] = make_float2(hs0, hs1);
}

__global__ __launch_bounds__(256) void scan_phase3(
    const float* __restrict__ bfw,
    const float* __restrict__ bbw,
    float* __restrict__ Y)
{
    const int t    = blockIdx.x * 256 + threadIdx.x;   // 0..65535
    const int h    = (t & 255) * 2;
    const int c    = (t >> 8) & 7;
    const int bi   = (t >> 11) & 15;
    const int dir  = t >> 15;
    const int lane = dir * 8192 + bi * 512 + h;

    const float* bias = dir ? bbw : bfw;
    const float2 bz = *(const float2*)(bias + h);
    const float2 bf = *(const float2*)(bias + HID + h);
    const float2 bo = *(const float2*)(bias + 2 * HID + h);

    const int s0 = dir ? (SEQ - 1 - c * CHLEN) : (c * CHLEN);
    const long long step2  = (dir ? -(long long)(BATCH * NCOLS)   : (long long)(BATCH * NCOLS)) / 2;
    const long long ystep2 = (dir ? -(long long)(BATCH * 2 * HID) : (long long)(BATCH * 2 * HID)) / 2;
    const __half2* gp = (const __half2*)(g_G + ((long long)(s0 * BATCH + bi)) * NCOLS
                                         + dir * 3 * HID + h);
    float2* yp = (float2*)(Y + ((long long)(s0 * BATCH + bi)) * (2 * HID) + dir * HID + h);

    __half2 zc[SCH], fc[SCH], oc[SCH];
#pragma unroll
    for (int j = 0; j < SCH; j++) {
        zc[j] = __ldcs(gp);
        fc[j] = __ldcs(gp + HID / 2);
        oc[j] = __ldcs(gp + HID);
        gp += step2;
    }

    // Inline chunk combine: serial over chunks < c (uniform per block,
    // coalesced float2 loads, A/C are L2-resident ~1MB).
    float hs0 = 0.0f, hs1 = 0.0f;
    for (int cc = 0; cc < c; cc++) {
        float2 Av = *(const float2*)&g_A[cc * NLANE + lane];
        float2 Cv = *(const float2*)&g_C[cc * NLANE + lane];
        hs0 = fmaf(Av.x, hs0, Cv.x);
        hs1 = fmaf(Av.y, hs1, Cv.y);
    }

    const int NIT = CHLEN / SCH;  // 32
    for (int it = 0; it < NIT; it++) {
        __half2 zn[SCH], fn[SCH], on[SCH];
        if (it < NIT - 1) {
#pragma unroll
            for (int j = 0; j < SCH; j++) {
                zn[j] = __ldcs(gp);
                fn[j] = __ldcs(gp + HID / 2);
                on[j] = __ldcs(gp + HID);
                gp += step2;
            }
        }
#pragma unroll
        for (int j = 0; j < SCH; j++) {
            float2 zv = __half22float2(zc[j]);
            float2 fv = __half22float2(fc[j]);
            float2 ov = __half22float2(oc[j]);
            float z0 = tanh_(zv.x + bz.x), z1 = tanh_(zv.y + bz.y);
            float f0 = sigm_(fv.x + bf.x), f1 = sigm_(fv.y + bf.y);
            float o0 = sigm_(ov.x + bo.x), o1 = sigm_(ov.y + bo.y);
            hs0 = fmaf(f0, z0 - hs0, hs0);
            hs1 = fmaf(f1, z1 - hs1, hs1);
            __stcs(yp, make_float2(o0 * hs0, o1 * hs1));
            yp += ystep2;
        }
#pragma unroll
        for (int j = 0; j < SCH; j++) { zc[j] = zn[j]; fc[j] = fn[j]; oc[j] = on[j]; }
    }
}

// ---------------------------------------------------------------------------
// Launch
// ---------------------------------------------------------------------------
extern "C" void kernel_launch(void* const* d_in, const int* in_sizes, int n_in,
                              void* d_out, int out_size)
{
    const float* X   = (const float*)d_in[0];
    const float* Wfw = (const float*)d_in[1];
    const float* bfw = (const float*)d_in[2];
    const float* Wbw = (const float*)d_in[3];
    const float* bbw = (const float*)d_in[4];
    float* Y = (float*)d_out;

    cudaFuncAttributes pa;
    bool use_tc = false;
    if (cudaFuncGetAttributes(&pa, probe_kernel) == cudaSuccess)
        use_tc = (pa.sharedSizeBytes >= 4096);

    cvt_kernel<<<17920, 256>>>(X, Wfw, Wbw);

    if (use_tc) {
        cudaFuncSetAttribute(gemm_tc_kernel, cudaFuncAttributeMaxDynamicSharedMemorySize, GEMM_SMEM);
        gemm_tc_kernel<<<GEMM_CTAS, GEMM_THREADS, GEMM_SMEM>>>();

        // scan_phase1 as PDL consumer: may begin while the GEMM's o-gate
        // tiles are still executing (its z/f inputs are ready at trigger).
        cudaLaunchConfig_t cfg = {};
        cfg.gridDim  = dim3(65536 / 256, 1, 1);
        cfg.blockDim = dim3(256, 1, 1);
        cfg.dynamicSmemBytes = 0;
        cfg.stream = 0;
        cudaLaunchAttribute at[1];
        at[0].id = cudaLaunchAttributeProgrammaticStreamSerialization;
        at[0].val.programmaticStreamSerializationAllowed = 1;
        cfg.attrs = at;
        cfg.numAttrs = 1;
        cudaLaunchKernelEx(&cfg, scan_phase1, bfw, bbw);
    } else {
        dim3 ggrid(NCOLS / BN, MROWS / BM);   // (24, 256)
        gemm_fp16_kernel<<<ggrid, 256>>>();
        scan_phase1<<<65536 / 256, 256>>>(bfw, bbw);
    }

    scan_phase3<<<65536 / 256, 256>>>(bfw, bbw, Y);
}

// round 12
// speedup vs baseline: 1.1025x; 1.1025x over previous
#include <cuda_runtime.h>
#include <cuda_fp16.h>
#include <cuda_bf16.h>
#include <cstdint>

// ---------------------------------------------------------------------------
// Problem constants
// ---------------------------------------------------------------------------
#define SEQ   2048
#define BATCH 16
#define DIN   512
#define HID   512
#define MROWS (SEQ*BATCH)       // 32768
#define NCOLS (3*HID*2)         // 3072
#define KDIM  DIN               // 512

// Feature gate: tcgen05 only exists in an arch-specific (sm_103a/sm_100a) pass.
#if defined(__CUDA_ARCH__) && (defined(__CUDA_ARCH_FEAT_SM103_ALL) || defined(__CUDA_ARCH_FEAT_SM100_ALL))
#define HAS_TCGEN05 1
#else
#define HAS_TCGEN05 0
#endif

// Scratch (static device arrays; no allocation allowed)
__device__ __half g_G[(size_t)MROWS * NCOLS];   // pre-activation gates (fp16)
__device__ __half g_Xh[(size_t)MROWS * KDIM];   // X in fp16
__device__ __half g_Wh[(size_t)NCOLS * KDIM];   // [W_fw; W_bw] in fp16

// Chunked-scan aggregates: 16384 lanes x 16 chunks, layout [chunk][lane]
#define NLANE 16384
#define NCHK  16
#define CHLEN (SEQ / NCHK)      // 128
__device__ float g_A[NCHK * NLANE];
__device__ float g_C[NCHK * NLANE];

// ---------------------------------------------------------------------------
// Probe kernel: static smem size tells the host whether the loaded device
// code came from the arch-specific (tcgen05-capable) pass.
// ---------------------------------------------------------------------------
__global__ void probe_kernel(float* p) {
#if HAS_TCGEN05
    __shared__ volatile float s[2048];
#else
    __shared__ volatile float s[64];
#endif
    s[threadIdx.x & 63] = p[0];
    p[1] = s[(threadIdx.x + 1) & 63];
}

// ---------------------------------------------------------------------------
// Common helpers
// ---------------------------------------------------------------------------
__device__ __forceinline__ uint32_t smem_to_u32(const void* p) {
    uint32_t a;
    asm("{ .reg .u64 t; cvta.to.shared.u64 t, %1; cvt.u32.u64 %0, t; }" : "=r"(a) : "l"(p));
    return a;
}

__device__ __forceinline__ float ex2f(float x) {
    float y; asm("ex2.approx.ftz.f32 %0, %1;" : "=f"(y) : "f"(x)); return y;
}
__device__ __forceinline__ float rcpf(float x) {
    float y; asm("rcp.approx.ftz.f32 %0, %1;" : "=f"(y) : "f"(x)); return y;
}
__device__ __forceinline__ float sigm_(float x) {
    return rcpf(1.0f + ex2f(-1.4426950408889634f * x));
}
__device__ __forceinline__ float tanh_(float x) {
    return fmaf(2.0f, rcpf(1.0f + ex2f(-2.8853900817779268f * x)), -1.0f);
}

// ---------------------------------------------------------------------------
// Kernel 0: fp32 -> fp16 conversion (X, W_fw, W_bw)
// ---------------------------------------------------------------------------
__global__ __launch_bounds__(256) void cvt_kernel(
    const float* __restrict__ X,
    const float* __restrict__ Wfw,
    const float* __restrict__ Wbw)
{
    const long long NX = (long long)MROWS * KDIM;     // 16777216
    const long long NW = (long long)(3 * HID) * KDIM; // 786432 per direction
    long long i = ((long long)blockIdx.x * blockDim.x + threadIdx.x) * 4;

    const float* src;
    __half* dst;
    if (i < NX)           { src = X   + i;             dst = g_Xh + i; }
    else if (i < NX + NW) { src = Wfw + (i - NX);      dst = g_Wh + (i - NX); }
    else                  { src = Wbw + (i - NX - NW); dst = g_Wh + (i - NX); }

    float4 v = __ldcs((const float4*)src);
    *(__half2*)dst       = __floats2half2_rn(v.x, v.y);
    *(__half2*)(dst + 2) = __floats2half2_rn(v.z, v.w);
}

// ===========================================================================
// GEMM path A: tcgen05, M=128 x N=256 tiles, 1 CTA/SM, 4-stage cp.async
// pipeline, TMEM double-buffered epilogue overlap. Natural tile order (R9).
// ===========================================================================
#define GBM 128
#define GBN 256
#define GBK 64
#define NKCH (KDIM / GBK)        // 8
#define STAGES 4
#define STAGE_A 16384            // 128 rows x 128B
#define STAGE_B 32768            // 256 rows x 128B
#define SMEM_A_OFF 1024
#define SMEM_B_OFF (1024 + STAGES * STAGE_A)          // 66560
#define GEMM_SMEM  (SMEM_B_OFF + STAGES * STAGE_B)    // 197632
#define N_MTILE (MROWS / GBM)    // 256
#define N_NTILE (NCOLS / GBN)    // 12
#define N_TILES (N_MTILE * N_NTILE)  // 3072
#define GEMM_CTAS 148
#define GEMM_THREADS 256

#if HAS_TCGEN05
#define SMEM_SWIZZLE_128B(o) ((o) ^ (((o) >> 3) & 0x70))

static constexpr uint64_t SMEM_DESC_BASE_SW128 =
    (uint64_t(2) << 61) | (uint64_t(1) << 46) | (uint64_t(64) << 32) | (uint64_t(1) << 16);
#define MAKE_SMEM_DESC(base_addr) \
    (SMEM_DESC_BASE_SW128 | ((uint64_t)((base_addr) >> 4) & 0x3FFF))

#define MBARRIER_INIT(addr, cnt) \
    asm volatile("mbarrier.init.shared.b64 [%0], %1;" :: "r"((uint32_t)(addr)), "r"((uint32_t)(cnt)) : "memory")

__device__ __forceinline__ void mbar_wait(uint32_t mbar, int parity) {
    uint32_t done;
    asm volatile(
        "{\n\t.reg .pred p;\n\t"
        "mbarrier.try_wait.parity.acquire.cta.shared::cta.b64 p, [%1], %2;\n\t"
        "selp.b32 %0, 1, 0, p;\n\t}"
        : "=r"(done) : "r"(mbar), "r"((uint32_t)parity) : "memory");
    if (!done) {
        asm volatile(
            "{\n\t.reg .pred P1;\n\t"
            "WAIT_LOOP_%=:\n\t"
            "mbarrier.try_wait.parity.acquire.cta.shared::cta.b64 P1, [%0], %1, 0x989680;\n\t"
            "@P1 bra.uni WAIT_DONE_%=;\n\t"
            "bra.uni WAIT_LOOP_%=;\n\t"
            "WAIT_DONE_%=:\n\t}"
            :: "r"(mbar), "r"((uint32_t)parity) : "memory");
    }
}

__device__ __forceinline__ uint32_t elect_one_pred() {
    uint32_t pred;
    asm volatile(
        "{\n\t.reg .pred p;\n\t"
        "elect.sync _|p, 0xFFFFFFFF;\n\t"
        "selp.b32 %0, 1, 0, p;\n\t}"
        : "=r"(pred));
    return pred;
}

#define TCGEN05_LD_32X32B_X32(r, tmem_addr) \
    asm volatile( \
        "tcgen05.ld.sync.aligned.32x32b.x32.b32 " \
        "{%0, %1, %2, %3, %4, %5, %6, %7, " \
        " %8, %9, %10, %11, %12, %13, %14, %15, " \
        " %16, %17, %18, %19, %20, %21, %22, %23, " \
        " %24, %25, %26, %27, %28, %29, %30, %31}, [%32];" \
        : "=r"((r)[0]),  "=r"((r)[1]),  "=r"((r)[2]),  "=r"((r)[3]), \
          "=r"((r)[4]),  "=r"((r)[5]),  "=r"((r)[6]),  "=r"((r)[7]), \
          "=r"((r)[8]),  "=r"((r)[9]),  "=r"((r)[10]), "=r"((r)[11]), \
          "=r"((r)[12]), "=r"((r)[13]), "=r"((r)[14]), "=r"((r)[15]), \
          "=r"((r)[16]), "=r"((r)[17]), "=r"((r)[18]), "=r"((r)[19]), \
          "=r"((r)[20]), "=r"((r)[21]), "=r"((r)[22]), "=r"((r)[23]), \
          "=r"((r)[24]), "=r"((r)[25]), "=r"((r)[26]), "=r"((r)[27]), \
          "=r"((r)[28]), "=r"((r)[29]), "=r"((r)[30]), "=r"((r)[31]) \
        : "r"(tmem_addr))

// idesc: dtype=F32 (1<<4), atype=btype=F16 (0), N=128 -> N/8<<17, M=128 -> M/16<<24
#define IDESC_F16 ((1u << 4) | ((128u / 8u) << 17) | ((128u / 16u) << 24))

__device__ __forceinline__ void mma_f16_ss(uint32_t d_tmem, uint64_t a_desc, uint64_t b_desc,
                                           uint32_t idesc, bool accum) {
    uint32_t en = accum ? 1u : 0u;
    asm volatile(
        "{\n\t.reg .pred p;\n\t"
        "setp.ne.u32 p, %4, 0;\n\t"
        "tcgen05.mma.cta_group::1.kind::f16 [%0], %1, %2, %3, {%5, %5, %5, %5}, p;\n\t}"
        :: "r"(d_tmem), "l"(a_desc), "l"(b_desc), "r"(idesc), "r"(en), "r"(0u)
        : "memory");
}

__device__ __forceinline__ void cp_async16(uint32_t dst, const void* src) {
    asm volatile("cp.async.cg.shared.global [%0], [%1], 16;" :: "r"(dst), "l"(src) : "memory");
}
__device__ __forceinline__ void cp_commit() {
    asm volatile("cp.async.commit_group;" ::: "memory");
}
template<int N> __device__ __forceinline__ void cp_wait() {
    asm volatile("cp.async.wait_group %0;" :: "n"(N) : "memory");
}

// Load one K-chunk (A: 128x64 halfs, B: 256x64 halfs) into stage st.
__device__ __forceinline__ void load_stage(uint32_t smem_base, int st, int kt,
                                           int m0, int n0, int tid)
{
    const __half* Asrc = g_Xh + (size_t)m0 * KDIM + kt * GBK;
    const __half* Bsrc = g_Wh + (size_t)n0 * KDIM + kt * GBK;
    uint32_t abase = smem_base + SMEM_A_OFF + st * STAGE_A;
    uint32_t bbase = smem_base + SMEM_B_OFF + st * STAGE_B;
#pragma unroll
    for (int i = 0; i < 4; i++) {                 // A: 1024 16B-chunks
        int chunk = i * GEMM_THREADS + tid;
        int row   = chunk >> 3;
        int c16   = chunk & 7;
        uint32_t off = SMEM_SWIZZLE_128B((uint32_t)(row * 128 + c16 * 16));
        cp_async16(abase + off, Asrc + (size_t)row * KDIM + c16 * 8);
    }
#pragma unroll
    for (int i = 0; i < 8; i++) {                 // B: 2048 16B-chunks
        int chunk = i * GEMM_THREADS + tid;
        int row   = chunk >> 3;
        int c16   = chunk & 7;
        uint32_t off = SMEM_SWIZZLE_128B((uint32_t)(row * 128 + c16 * 16));
        cp_async16(bbase + off, Bsrc + (size_t)row * KDIM + c16 * 8);
    }
    cp_commit();
}

// Epilogue: TMEM fp32 (128 lanes x 256 cols) -> fp16 -> streaming store.
__device__ __forceinline__ void epilogue_tile(uint32_t tmem_d, int m0, int n0,
                                              int wid, int lid)
{
    asm volatile("tcgen05.fence::after_thread_sync;" ::: "memory");
    const int sub     = wid & 3;
    const int colhalf = wid >> 2;
    const int m = m0 + sub * 32 + lid;
    __half* gout = g_G + (size_t)m * NCOLS + n0 + colhalf * 128;
    const uint32_t tbase = tmem_d + colhalf * 128;
#pragma unroll
    for (int c0 = 0; c0 < 128; c0 += 32) {
        uint32_t d[32];
        TCGEN05_LD_32X32B_X32(d, tbase + c0);
        asm volatile("tcgen05.wait::ld.sync.aligned;" ::: "memory");
        uint32_t hp[16];
#pragma unroll
        for (int c = 0; c < 16; c++) {
            __half2 h2 = __floats2half2_rn(__uint_as_float(d[2 * c]),
                                           __uint_as_float(d[2 * c + 1]));
            hp[c] = *(uint32_t*)&h2;
        }
#pragma unroll
        for (int q = 0; q < 4; q++) {
            uint4 v = make_uint4(hp[q * 4], hp[q * 4 + 1], hp[q * 4 + 2], hp[q * 4 + 3]);
            __stcs((uint4*)(gout + c0 + q * 8), v);
        }
    }
    asm volatile("tcgen05.fence::before_thread_sync;" ::: "memory");
}
#endif  // HAS_TCGEN05

#define MBAR(s) (smem_base + 16 + (s) * 8)
#define SLOT_FINAL 4

__global__ void __launch_bounds__(GEMM_THREADS, 1) __cluster_dims__(1, 1, 1) gemm_tc_kernel()
{
#if HAS_TCGEN05
    extern __shared__ char smem[];
    uint32_t smem_base = smem_to_u32(smem);
    const int tid = threadIdx.x;
    const int wid = tid >> 5;
    const int lid = tid & 31;

    if (tid < 5) MBARRIER_INIT(MBAR(tid), 1);   // 0-3: stage reuse, 4: tile-final
    if (wid == 0) {
        asm volatile("tcgen05.alloc.cta_group::1.sync.aligned.shared::cta.b32 [%0], %1;"
            :: "r"(smem_base), "r"(512u) : "memory");
        asm volatile("tcgen05.relinquish_alloc_permit.cta_group::1.sync.aligned;");
    }
    __syncthreads();

    uint32_t tmem;
    asm volatile("ld.shared.b32 %0, [%1];" : "=r"(tmem) : "r"(smem_base));

    int ph[5] = {0, 0, 0, 0, 0};
    int buf = 0;
    int prev_m0 = 0, prev_n0 = 0;
    bool has_prev = false;

    for (int tile = blockIdx.x; tile < N_TILES; tile += GEMM_CTAS) {
        const int m0 = (tile / N_NTILE) * GBM;
        const int n0 = (tile % N_NTILE) * GBN;
        const uint32_t tmem_d = tmem + buf * 256;

        load_stage(smem_base, 0, 0, m0, n0, tid);
        load_stage(smem_base, 1, 1, m0, n0, tid);
        if (has_prev) { mbar_wait(MBAR(SLOT_FINAL), ph[SLOT_FINAL]); ph[SLOT_FINAL] ^= 1; }
        load_stage(smem_base, 2, 2, m0, n0, tid);

#pragma unroll
        for (int kt = 0; kt < NKCH; kt++) {
            const int st = kt % STAGES;
            if (kt == NKCH - 1)      cp_wait<0>();
            else if (kt == NKCH - 2) cp_wait<1>();
            else                     cp_wait<2>();
            __syncthreads();
            asm volatile("fence.proxy.async.shared::cta;" ::: "memory");

            if (wid == 0) {
                if (elect_one_pred()) {
                    uint64_t ad = MAKE_SMEM_DESC(smem_base + SMEM_A_OFF + st * STAGE_A);
                    uint64_t bd = MAKE_SMEM_DESC(smem_base + SMEM_B_OFF + st * STAGE_B);
#pragma unroll
                    for (int nh = 0; nh < 2; nh++)
#pragma unroll
                        for (int k = 0; k < 4; k++)   // 4 x K=16 per 64-half chunk
                            mma_f16_ss(tmem_d + nh * 128,
                                       ad + k * 2,
                                       bd + nh * 1024 + k * 2,   // +128 B-rows
                                       IDESC_F16,
                                       !(kt == 0 && k == 0));
                    asm volatile(
                        "tcgen05.commit.cta_group::1.mbarrier::arrive::one.shared::cluster.b64 [%0];"
                        :: "r"(MBAR(kt == NKCH - 1 ? SLOT_FINAL : st)) : "memory");
                }
            }

            if (kt >= 1) {
                const int ws = (kt - 1) % STAGES;
                mbar_wait(MBAR(ws), ph[ws]); ph[ws] ^= 1;
            }
            if (kt + 3 < NKCH)
                load_stage(smem_base, (kt + 3) % STAGES, kt + 3, m0, n0, tid);
        }

        // Drain the PREVIOUS tile's accumulator while this tile's MMAs run.
        if (has_prev) {
            epilogue_tile(tmem + (buf ^ 1) * 256, prev_m0, prev_n0, wid, lid);
        }

        has_prev = true;
        prev_m0 = m0; prev_n0 = n0;
        buf ^= 1;
    }

    // Tail: drain the last tile.
    if (has_prev) {
        mbar_wait(MBAR(SLOT_FINAL), ph[SLOT_FINAL]); ph[SLOT_FINAL] ^= 1;
        epilogue_tile(tmem + (buf ^ 1) * 256, prev_m0, prev_n0, wid, lid);
    }

    __syncthreads();
    if (wid == 0)
        asm volatile("tcgen05.dealloc.cta_group::1.sync.aligned.b32 %0, %1;" :: "r"(tmem), "r"(512u));
#endif  // HAS_TCGEN05
}

// ===========================================================================
// GEMM path B (fallback, baseline ISA): fp16 mma.sync.m16n8k16
// ===========================================================================
#define BM 128
#define BN 128
#define BK 32
#define HPAD 40   // 32 + 8 halves padding

__global__ __launch_bounds__(256) void gemm_fp16_kernel()
{
    __shared__ __half sA[BM][HPAD];
    __shared__ __half sB[BN][HPAD];

    const int tid  = threadIdx.x;
    const int n0   = blockIdx.x * BN;
    const int m0   = blockIdx.y * BM;

    const __half* Asrc = g_Xh + (size_t)m0 * KDIM;
    const __half* Bsrc = g_Wh + (size_t)n0 * KDIM;

    const int warp = tid >> 5;
    const int lane = tid & 31;
    const int wm   = warp >> 1;
    const int wn   = warp & 1;
    const int lr   = lane >> 2;
    const int lc   = lane & 3;

    float4 ra[2], rb[2];

#pragma unroll
    for (int i = 0; i < 2; i++) {
        int slot = tid + i * 256;
        int row  = slot >> 2;
        int c8   = slot & 3;
        ra[i] = *(const float4*)(Asrc + (size_t)row * KDIM + c8 * 8);
        rb[i] = *(const float4*)(Bsrc + (size_t)row * KDIM + c8 * 8);
    }
#pragma unroll
    for (int i = 0; i < 2; i++) {
        int slot = tid + i * 256;
        int row  = slot >> 2;
        int c8   = slot & 3;
        *(float4*)&sA[row][c8 * 8] = ra[i];
        *(float4*)&sB[row][c8 * 8] = rb[i];
    }
    __syncthreads();

    float acc[2][8][4];
#pragma unroll
    for (int mt = 0; mt < 2; mt++)
#pragma unroll
        for (int nt = 0; nt < 8; nt++)
#pragma unroll
            for (int r = 0; r < 4; r++) acc[mt][nt][r] = 0.0f;

    const int NK = KDIM / BK;  // 16
    for (int kt = 0; kt < NK; kt++) {
        if (kt < NK - 1) {
#pragma unroll
            for (int i = 0; i < 2; i++) {
                int slot = tid + i * 256;
                int row  = slot >> 2;
                int c8   = slot & 3;
                ra[i] = *(const float4*)(Asrc + (size_t)row * KDIM + (kt + 1) * BK + c8 * 8);
                rb[i] = *(const float4*)(Bsrc + (size_t)row * KDIM + (kt + 1) * BK + c8 * 8);
            }
        }

#pragma unroll
        for (int ks = 0; ks < 2; ks++) {
            const int kc = ks * 16 + lc * 2;
            uint32_t afr[2][4];
            uint32_t bfr[8][2];
#pragma unroll
            for (int mt = 0; mt < 2; mt++) {
                int r = wm * 32 + mt * 16 + lr;
                afr[mt][0] = *(const uint32_t*)&sA[r    ][kc    ];
                afr[mt][1] = *(const uint32_t*)&sA[r + 8][kc    ];
                afr[mt][2] = *(const uint32_t*)&sA[r    ][kc + 8];
                afr[mt][3] = *(const uint32_t*)&sA[r + 8][kc + 8];
            }
#pragma unroll
            for (int nt = 0; nt < 8; nt++) {
                int nr = wn * 64 + nt * 8 + lr;
                bfr[nt][0] = *(const uint32_t*)&sB[nr][kc    ];
                bfr[nt][1] = *(const uint32_t*)&sB[nr][kc + 8];
            }
#pragma unroll
            for (int mt = 0; mt < 2; mt++)
#pragma unroll
                for (int nt = 0; nt < 8; nt++)
                    asm volatile(
                        "mma.sync.aligned.m16n8k16.row.col.f32.f16.f16.f32 "
                        "{%0,%1,%2,%3}, {%4,%5,%6,%7}, {%8,%9}, {%0,%1,%2,%3};"
                        : "+f"(acc[mt][nt][0]), "+f"(acc[mt][nt][1]),
                          "+f"(acc[mt][nt][2]), "+f"(acc[mt][nt][3])
                        : "r"(afr[mt][0]), "r"(afr[mt][1]), "r"(afr[mt][2]), "r"(afr[mt][3]),
                          "r"(bfr[nt][0]), "r"(bfr[nt][1]));
        }

        __syncthreads();
        if (kt < NK - 1) {
#pragma unroll
            for (int i = 0; i < 2; i++) {
                int slot = tid + i * 256;
                int row  = slot >> 2;
                int c8   = slot & 3;
                *(float4*)&sA[row][c8 * 8] = ra[i];
                *(float4*)&sB[row][c8 * 8] = rb[i];
            }
            __syncthreads();
        }
    }

#pragma unroll
    for (int mt = 0; mt < 2; mt++) {
#pragma unroll
        for (int nt = 0; nt < 8; nt++) {
            int r0  = m0 + wm * 32 + mt * 16 + lr;
            int col = n0 + wn * 64 + nt * 8 + lc * 2;
            __half2 h0 = __floats2half2_rn(acc[mt][nt][0], acc[mt][nt][1]);
            __half2 h1 = __floats2half2_rn(acc[mt][nt][2], acc[mt][nt][3]);
            *(__half2*)(g_G + (size_t)r0 * NCOLS + col)       = h0;
            *(__half2*)(g_G + (size_t)(r0 + 8) * NCOLS + col) = h1;
        }
    }
}

// ===========================================================================
// Chunked scan: 2 passes, 16 chunks of 128 steps. Each thread handles an
// (h, h+1) pair via half2. 131072 threads each; p3 inlines the chunk combine.
// ===========================================================================
#define SCH 8   // inner prefetch chunk

__global__ __launch_bounds__(256) void scan_phase1(
    const float* __restrict__ bfw,
    const float* __restrict__ bbw)
{
    const int t    = blockIdx.x * 256 + threadIdx.x;   // 0..131071
    const int h    = (t & 255) * 2;
    const int c    = (t >> 8) & 15;
    const int bi   = (t >> 12) & 15;
    const int dir  = t >> 16;
    const int lane = dir * 8192 + bi * 512 + h;

    const float* bias = dir ? bbw : bfw;
    const float2 bz = *(const float2*)(bias + h);
    const float2 bf = *(const float2*)(bias + HID + h);

    const int s0 = dir ? (SEQ - 1 - c * CHLEN) : (c * CHLEN);
    const long long step2 = (dir ? -(long long)(BATCH * NCOLS) : (long long)(BATCH * NCOLS)) / 2;
    const __half2* gp = (const __half2*)(g_G + ((long long)(s0 * BATCH + bi)) * NCOLS
                                         + dir * 3 * HID + h);

    __half2 zc[SCH], fc[SCH];
#pragma unroll
    for (int j = 0; j < SCH; j++) {
        zc[j] = __ldcs(gp);
        fc[j] = __ldcs(gp + HID / 2);
        gp += step2;
    }

    float hs0 = 0.0f, hs1 = 0.0f, A0 = 1.0f, A1 = 1.0f;
    const int NIT = CHLEN / SCH;  // 16
    for (int it = 0; it < NIT; it++) {
        __half2 zn[SCH], fn[SCH];
        if (it < NIT - 1) {
#pragma unroll
            for (int j = 0; j < SCH; j++) {
                zn[j] = __ldcs(gp);
                fn[j] = __ldcs(gp + HID / 2);
                gp += step2;
            }
        }
#pragma unroll
        for (int j = 0; j < SCH; j++) {
            float2 zv = __half22float2(zc[j]);
            float2 fv = __half22float2(fc[j]);
            float z0 = tanh_(zv.x + bz.x), z1 = tanh_(zv.y + bz.y);
            float f0 = sigm_(fv.x + bf.x), f1 = sigm_(fv.y + bf.y);
            hs0 = fmaf(f0, z0 - hs0, hs0);
            hs1 = fmaf(f1, z1 - hs1, hs1);
            A0 *= (1.0f - f0);
            A1 *= (1.0f - f1);
        }
#pragma unroll
        for (int j = 0; j < SCH; j++) { zc[j] = zn[j]; fc[j] = fn[j]; }
    }

    *(float2*)&g_A[c * NLANE + lane] = make_float2(A0, A1);
    *(float2*)&g_C[c * NLANE + lane] = make_float2(hs0, hs1);
}

__global__ __launch_bounds__(256) void scan_phase3(
    const float* __restrict__ bfw,
    const float* __restrict__ bbw,
    float* __restrict__ Y)
{
    const int t    = blockIdx.x * 256 + threadIdx.x;   // 0..131071
    const int h    = (t & 255) * 2;
    const int c    = (t >> 8) & 15;
    const int bi   = (t >> 12) & 15;
    const int dir  = t >> 16;
    const int lane = dir * 8192 + bi * 512 + h;

    const float* bias = dir ? bbw : bfw;
    const float2 bz = *(const float2*)(bias + h);
    const float2 bf = *(const float2*)(bias + HID + h);
    const float2 bo = *(const float2*)(bias + 2 * HID + h);

    const int s0 = dir ? (SEQ - 1 - c * CHLEN) : (c * CHLEN);
    const long long step2  = (dir ? -(long long)(BATCH * NCOLS)   : (long long)(BATCH * NCOLS)) / 2;
    const long long ystep2 = (dir ? -(long long)(BATCH * 2 * HID) : (long long)(BATCH * 2 * HID)) / 2;
    const __half2* gp = (const __half2*)(g_G + ((long long)(s0 * BATCH + bi)) * NCOLS
                                         + dir * 3 * HID + h);
    float2* yp = (float2*)(Y + ((long long)(s0 * BATCH + bi)) * (2 * HID) + dir * HID + h);

    __half2 zc[SCH], fc[SCH], oc[SCH];
#pragma unroll
    for (int j = 0; j < SCH; j++) {
        zc[j] = __ldcs(gp);
        fc[j] = __ldcs(gp + HID / 2);
        oc[j] = __ldcs(gp + HID);
        gp += step2;
    }

    // Inline chunk combine: serial over chunks < c (uniform per block,
    // coalesced float2 loads, A/C are L2-resident ~2MB).
    float hs0 = 0.0f, hs1 = 0.0f;
    for (int cc = 0; cc < c; cc++) {
        float2 Av = *(const float2*)&g_A[cc * NLANE + lane];
        float2 Cv = *(const float2*)&g_C[cc * NLANE + lane];
        hs0 = fmaf(Av.x, hs0, Cv.x);
        hs1 = fmaf(Av.y, hs1, Cv.y);
    }

    const int NIT = CHLEN / SCH;  // 16
    for (int it = 0; it < NIT; it++) {
        __half2 zn[SCH], fn[SCH], on[SCH];
        if (it < NIT - 1) {
#pragma unroll
            for (int j = 0; j < SCH; j++) {
                zn[j] = __ldcs(gp);
                fn[j] = __ldcs(gp + HID / 2);
                on[j] = __ldcs(gp + HID);
                gp += step2;
            }
        }
#pragma unroll
        for (int j = 0; j < SCH; j++) {
            float2 zv = __half22float2(zc[j]);
            float2 fv = __half22float2(fc[j]);
            float2 ov = __half22float2(oc[j]);
            float z0 = tanh_(zv.x + bz.x), z1 = tanh_(zv.y + bz.y);
            float f0 = sigm_(fv.x + bf.x), f1 = sigm_(fv.y + bf.y);
            float o0 = sigm_(ov.x + bo.x), o1 = sigm_(ov.y + bo.y);
            hs0 = fmaf(f0, z0 - hs0, hs0);
            hs1 = fmaf(f1, z1 - hs1, hs1);
            __stcs(yp, make_float2(o0 * hs0, o1 * hs1));
            yp += ystep2;
        }
#pragma unroll
        for (int j = 0; j < SCH; j++) { zc[j] = zn[j]; fc[j] = fn[j]; oc[j] = on[j]; }
    }
}

// ---------------------------------------------------------------------------
// Launch
// ---------------------------------------------------------------------------
extern "C" void kernel_launch(void* const* d_in, const int* in_sizes, int n_in,
                              void* d_out, int out_size)
{
    const float* X   = (const float*)d_in[0];
    const float* Wfw = (const float*)d_in[1];
    const float* bfw = (const float*)d_in[2];
    const float* Wbw = (const float*)d_in[3];
    const float* bbw = (const float*)d_in[4];
    float* Y = (float*)d_out;

    cudaFuncAttributes pa;
    bool use_tc = false;
    if (cudaFuncGetAttributes(&pa, probe_kernel) == cudaSuccess)
        use_tc = (pa.sharedSizeBytes >= 4096);

    cvt_kernel<<<17920, 256>>>(X, Wfw, Wbw);

    if (use_tc) {
        cudaFuncSetAttribute(gemm_tc_kernel, cudaFuncAttributeMaxDynamicSharedMemorySize, GEMM_SMEM);
        gemm_tc_kernel<<<GEMM_CTAS, GEMM_THREADS, GEMM_SMEM>>>();
    } else {
        dim3 ggrid(NCOLS / BN, MROWS / BM);   // (24, 256)
        gemm_fp16_kernel<<<ggrid, 256>>>();
    }

    scan_phase1<<<131072 / 256, 256>>>(bfw, bbw);
    scan_phase3<<<131072 / 256, 256>>>(bfw, bbw, Y);
}